// round 11
// baseline (speedup 1.0000x reference)
#include <cuda_runtime.h>
#include <cstdint>

// ---------------------------------------------------------------------------
// Problem dims
// ---------------------------------------------------------------------------
#define TSTEPS 512
#define NB     64
#define HID    256
#define MROWS  (TSTEPS * NB)      // 32768
#define NCOLS  1024               // 4*HID
#define KDIM   256
#define NCLASS 5

#define NJ   8                     // j per CTA
#define NBL  32                    // batches per CTA
#define FULLMASK 0xffffffffu
#define REC_SMEM (3 * 8192 * 4)    // 96 KB: layer2 = W2 + U2 + staging; layer1 uses 64KB of it

// ---------------------------------------------------------------------------
// Scratch (static __device__ arrays: allocation-free, allowed)
// ---------------------------------------------------------------------------
__device__ __align__(128) float g_Z  [2u * MROWS * NCOLS];        // layer-1 gate preacts
__device__ __align__(128) float g_H2 [2u * MROWS * HID];          // layer-2 outputs [t,b,j]
__device__ __align__(128) float g_hT1[2u * TSTEPS * HID * NB];    // FULL history h1 [dir][t][j][b]
__device__ __align__(128) float g_hT2[2u * TSTEPS * HID * NB];    // FULL history h2 [dir][t][j][b]
__device__ __align__(128) unsigned g_flags[8][32];                // [0..3]=layer1 grp, [4..7]=layer2 grp
__device__ int g_tok32 = 1;                                       // token dtype flag

// ---------------------------------------------------------------------------
// Single-hop message passing primitives
// ---------------------------------------------------------------------------
__device__ __forceinline__ unsigned ld_acquire(const unsigned* p) {
    unsigned v;
    asm volatile("ld.acquire.gpu.global.u32 %0, [%1];" : "=r"(v) : "l"(p) : "memory");
    return v;
}
__device__ __forceinline__ void st_release(unsigned* p, unsigned v) {
    asm volatile("st.release.gpu.global.u32 [%0], %1;" :: "l"(p), "r"(v) : "memory");
}

// ---------------------------------------------------------------------------
// Math helpers
// ---------------------------------------------------------------------------
__device__ __forceinline__ float fsig(float x) {
    x = fminf(fmaxf(x, -30.f), 30.f);
    return __fdividef(1.f, 1.f + __expf(-x));
}
__device__ __forceinline__ float ftanh_(float x) {
    x = fminf(fmaxf(x, -15.f), 15.f);
    float e = __expf(-2.f * x);
    return __fdividef(1.f - e, 1.f + e);
}
__device__ __forceinline__ int load_token(const void* tokens, int is32, int idx) {
    if (is32) return ((const int*)tokens)[idx];
    return (int)((const long long*)tokens)[idx];
}

// ---------------------------------------------------------------------------
// Prep: zero flags (graph replays) + token dtype probe.
// ---------------------------------------------------------------------------
__global__ void prep_kernel(const void* __restrict__ tokens) {
    __shared__ int flag;
    const int tid = threadIdx.x;
    if (tid < 256) ((unsigned*)g_flags)[tid] = 0u;
    if (tid == 0) flag = 0;
    __syncthreads();
    const int* p = (const int*)tokens;
    int local = 0;
    for (int i = 1 + 2 * tid; i < MROWS; i += 2 * 256) local |= p[i];
    if (local) atomicOr(&flag, 1);
    __syncthreads();
    if (tid == 0) g_tok32 = (flag != 0) ? 1 : 0;
}

// ---------------------------------------------------------------------------
// SGEMM (layer-1 input): Z[dir] = embed(tokens) @ W1[dir] + b1[dir]
// ---------------------------------------------------------------------------
__global__ void __launch_bounds__(256) gemm_kernel(
    const float* __restrict__ embed,
    const void*  __restrict__ tokens,
    const float* __restrict__ W_fw,
    const float* __restrict__ W_bw,
    const float* __restrict__ b_fw,
    const float* __restrict__ b_bw)
{
    __shared__ __align__(16) float As[16][132];
    __shared__ __align__(16) float Bs[16][128];
    __shared__ int sTok[128];

    const int tid = threadIdx.x;
    const int dir = blockIdx.z;
    const int m0  = blockIdx.y * 128;
    const int n0  = blockIdx.x * 128;

    const float* Wm   = dir ? W_bw : W_fw;
    const float* bias = dir ? b_bw : b_fw;

    if (tid < 128) {
        int r = m0 + tid;
        int s = r >> 6, b = r & 63;
        int tt = (dir == 0) ? s : (TSTEPS - 1 - s);
        sTok[tid] = load_token(tokens, g_tok32, b * TSTEPS + tt);
    }
    __syncthreads();

    const int ty = tid >> 4;
    const int tx = tid & 15;

    float acc[8][8];
#pragma unroll
    for (int i = 0; i < 8; i++)
#pragma unroll
        for (int j = 0; j < 8; j++) acc[i][j] = 0.f;

    for (int kt = 0; kt < KDIM; kt += 16) {
#pragma unroll
        for (int i = 0; i < 2; i++) {
            int idx = tid + i * 256;
            int m   = idx >> 2;
            int kq  = idx & 3;
            const float* arow = embed + (size_t)sTok[m] * KDIM;
            float4 v = *(const float4*)(arow + kt + kq * 4);
            As[kq * 4 + 0][m] = v.x;
            As[kq * 4 + 1][m] = v.y;
            As[kq * 4 + 2][m] = v.z;
            As[kq * 4 + 3][m] = v.w;
        }
#pragma unroll
        for (int i = 0; i < 2; i++) {
            int idx = tid + i * 256;
            int k   = idx >> 5;
            int nq  = idx & 31;
            *(float4*)&Bs[k][nq * 4] =
                *(const float4*)(Wm + (size_t)(kt + k) * NCOLS + n0 + nq * 4);
        }
        __syncthreads();

#pragma unroll
        for (int kk = 0; kk < 16; kk++) {
            float a[8], bb[8];
            *(float4*)&a[0]  = *(const float4*)&As[kk][ty * 8];
            *(float4*)&a[4]  = *(const float4*)&As[kk][ty * 8 + 4];
            *(float4*)&bb[0] = *(const float4*)&Bs[kk][tx * 8];
            *(float4*)&bb[4] = *(const float4*)&Bs[kk][tx * 8 + 4];
#pragma unroll
            for (int i = 0; i < 8; i++)
#pragma unroll
                for (int j = 0; j < 8; j++)
                    acc[i][j] = fmaf(a[i], bb[j], acc[i][j]);
        }
        __syncthreads();
    }

    float bv[8];
#pragma unroll
    for (int j = 0; j < 8; j++) bv[j] = bias[n0 + tx * 8 + j];

    float* Cd = g_Z + (size_t)dir * MROWS * NCOLS;
#pragma unroll
    for (int i = 0; i < 8; i++) {
        size_t r = (size_t)(m0 + ty * 8 + i);
        float* cp = Cd + r * NCOLS + n0 + tx * 8;
        float4 o0, o1;
        o0.x = acc[i][0] + bv[0]; o0.y = acc[i][1] + bv[1];
        o0.z = acc[i][2] + bv[2]; o0.w = acc[i][3] + bv[3];
        o1.x = acc[i][4] + bv[4]; o1.y = acc[i][5] + bv[5];
        o1.z = acc[i][6] + bv[6]; o1.w = acc[i][7] + bv[7];
        *(float4*)cp       = o0;
        *((float4*)cp + 1) = o1;
    }
}

// ---------------------------------------------------------------------------
// DUAL-WAVEFRONT recurrence: 256 CTAs, 2/SM co-resident (96KB smem, <=128 regs).
// Blocks 0..127  = LAYER 1 (R7-proven tick; publishes h1[t] + flags1).
// Blocks 128..255 = LAYER 2 (waits flags1>=t+1 & flags2>=t; W2-matvec over
//                   h1[t], U2-matvec over h2[t-1]; publishes h2[t] + flags2).
// hT buffers are FULL-HISTORY [dir][t][j][b] -> layer-1 free-runs ahead with
// no WAR hazard and no back-pressure; both 512-tick chains overlap in time.
// ---------------------------------------------------------------------------
__global__ void __launch_bounds__(256, 2) rec_dual_kernel(
    const float* __restrict__ U1_fw, const float* __restrict__ U1_bw,
    const float* __restrict__ W2_fw, const float* __restrict__ W2_bw,
    const float* __restrict__ b2_fw, const float* __restrict__ b2_bw,
    const float* __restrict__ U2_fw, const float* __restrict__ U2_bw)
{
    extern __shared__ float smem[];

    const int cid  = blockIdx.x;
    const bool isL2 = (cid >= 128);
    const int c    = cid & 127;
    const int dir  = c >> 6;
    const int rem  = c & 63;
    const int jb   = rem >> 1;          // 0..31 (flag index)
    const int bb   = rem & 1;
    const int j0   = jb * NJ;
    const int b0   = bb * NBL;
    const int tid  = threadIdx.x;
    const int lane = tid & 31;
    const int bl   = tid >> 3;          // 0..31
    const int jl   = tid & 7;           // 0..7
    const int b    = b0 + bl;
    const int j    = j0 + jl;

    const int grp = dir * 2 + bb;
    unsigned* flags1 = g_flags[grp];
    unsigned* flags2 = g_flags[4 + grp];

    float* hist1 = g_hT1 + (size_t)dir * TSTEPS * 16384;
    float* hist2 = g_hT2 + (size_t)dir * TSTEPS * 16384;

    if (!isL2) {
        // ===================== LAYER 1 =====================
        float* sU1 = smem;              // 8192 floats
        float* s_h = smem + 8192;       // 8192 floats

        const float* U1 = dir ? U1_bw : U1_fw;
        for (int idx = tid; idx < NJ * 4 * KDIM; idx += 256) {
            int g  = idx & 3;
            int jj = (idx >> 2) & (NJ - 1);
            int k  = idx >> 5;
            sU1[idx] = U1[(size_t)k * NCOLS + g * HID + j0 + jj];
        }
        __syncthreads();

        const unsigned a_sU1 = (unsigned)__cvta_generic_to_shared(sU1) + (unsigned)(jl * 16);
        const float* Zd = g_Z + (size_t)dir * MROWS * NCOLS;

        size_t zrow0 = (size_t)b * NCOLS;
        float4 z;
        z.x = __ldcs(&Zd[zrow0 + 0 * HID + j]);
        z.y = __ldcs(&Zd[zrow0 + 1 * HID + j]);
        z.z = __ldcs(&Zd[zrow0 + 2 * HID + j]);
        z.w = __ldcs(&Zd[zrow0 + 3 * HID + j]);

        float c1 = 0.f;

        for (int t = 0; t < TSTEPS; t++) {
            unsigned long long a01, a23;
            asm("mov.b64 %0,{%1,%2};" : "=l"(a01)
                : "r"(__float_as_uint(z.x)), "r"(__float_as_uint(z.y)));
            asm("mov.b64 %0,{%1,%2};" : "=l"(a23)
                : "r"(__float_as_uint(z.z)), "r"(__float_as_uint(z.w)));

            if (t > 0) {
                if (tid < 32) {
                    const unsigned tgt = (unsigned)t;
                    while (__ballot_sync(FULLMASK, ld_acquire(&flags1[lane]) < tgt)) { }
                }
                __syncthreads();

                const float* src = hist1 + (size_t)(t - 1) * 16384;
#pragma unroll
                for (int i = 0; i < 8; i++) {
                    int idx = tid + i * 256;
                    int jr  = idx >> 3;
                    int q   = idx & 7;
                    float4 v = __ldcg((const float4*)(src + jr * 64 + b0) + q);
                    *(float4*)&s_h[jr * NBL + q * 4] = v;
                }
                __syncthreads();

#pragma unroll 16
                for (int k = 0; k < KDIM; k++) {
                    float hv = s_h[k * NBL + bl];
                    unsigned long long hh, u01, u23;
                    asm("mov.b64 %0,{%1,%1};" : "=l"(hh) : "r"(__float_as_uint(hv)));
                    asm("ld.shared.v2.b64 {%0,%1},[%2];" : "=l"(u01), "=l"(u23)
                        : "r"(a_sU1 + (unsigned)(k * (NJ * 16))));
                    asm("fma.rn.f32x2 %0,%1,%2,%0;" : "+l"(a01) : "l"(u01), "l"(hh));
                    asm("fma.rn.f32x2 %0,%1,%2,%0;" : "+l"(a23) : "l"(u23), "l"(hh));
                }
            }

            unsigned r0, r1, r2, r3;
            asm("mov.b64 {%0,%1},%2;" : "=r"(r0), "=r"(r1) : "l"(a01));
            asm("mov.b64 {%0,%1},%2;" : "=r"(r2), "=r"(r3) : "l"(a23));
            float ig = fsig(__uint_as_float(r0));
            float fg = fsig(__uint_as_float(r1));
            float gg = ftanh_(__uint_as_float(r2));
            float og = fsig(__uint_as_float(r3));
            c1 = fg * c1 + ig * gg;
            float h1 = og * ftanh_(c1);

            hist1[(size_t)t * 16384 + j * 64 + b] = h1;

            __syncthreads();
            if (tid == 0) st_release(&flags1[jb], (unsigned)(t + 1));

            if (t + 1 < TSTEPS) {
                size_t zrow = ((size_t)(t + 1) * NB + b) * NCOLS;
                z.x = __ldcs(&Zd[zrow + 0 * HID + j]);
                z.y = __ldcs(&Zd[zrow + 1 * HID + j]);
                z.z = __ldcs(&Zd[zrow + 2 * HID + j]);
                z.w = __ldcs(&Zd[zrow + 3 * HID + j]);
            }
        }
    } else {
        // ===================== LAYER 2 =====================
        float* sW2 = smem;              // 8192 floats
        float* sU2 = smem + 8192;       // 8192 floats
        float* s_h = smem + 16384;      // 8192 floats (shared h1/h2 staging)

        const float* W2 = dir ? W2_bw : W2_fw;
        const float* U2 = dir ? U2_bw : U2_fw;
        const float* B2 = dir ? b2_bw : b2_fw;

        for (int idx = tid; idx < NJ * 4 * KDIM; idx += 256) {
            int g  = idx & 3;
            int jj = (idx >> 2) & (NJ - 1);
            int k  = idx >> 5;
            size_t src = (size_t)k * NCOLS + g * HID + j0 + jj;
            sW2[idx] = W2[src];
            sU2[idx] = U2[src];
        }
        __syncthreads();

        const unsigned a_sW2 = (unsigned)__cvta_generic_to_shared(sW2) + (unsigned)(jl * 16);
        const unsigned a_sU2 = (unsigned)__cvta_generic_to_shared(sU2) + (unsigned)(jl * 16);
        float* Hd2 = g_H2 + (size_t)dir * MROWS * HID;

        unsigned long long b2_01, b2_23;
        {
            float bx = B2[0 * HID + j], by = B2[1 * HID + j];
            float bz = B2[2 * HID + j], bw = B2[3 * HID + j];
            asm("mov.b64 %0,{%1,%2};" : "=l"(b2_01)
                : "r"(__float_as_uint(bx)), "r"(__float_as_uint(by)));
            asm("mov.b64 %0,{%1,%2};" : "=l"(b2_23)
                : "r"(__float_as_uint(bz)), "r"(__float_as_uint(bw)));
        }

        float c2 = 0.f;

        for (int t = 0; t < TSTEPS; t++) {
            // wait: warp0 -> flags1 >= t+1 (h1[t] ready); warp1 -> flags2 >= t
            if (tid < 32) {
                const unsigned tgt = (unsigned)(t + 1);
                while (__ballot_sync(FULLMASK, ld_acquire(&flags1[lane]) < tgt)) { }
            } else if (tid < 64 && t > 0) {
                const unsigned tgt = (unsigned)t;
                while (__ballot_sync(FULLMASK, ld_acquire(&flags2[lane]) < tgt)) { }
            }
            __syncthreads();

            // stage h1[t]
            {
                const float* src = hist1 + (size_t)t * 16384;
#pragma unroll
                for (int i = 0; i < 8; i++) {
                    int idx = tid + i * 256;
                    int jr  = idx >> 3;
                    int q   = idx & 7;
                    float4 v = __ldcg((const float4*)(src + jr * 64 + b0) + q);
                    *(float4*)&s_h[jr * NBL + q * 4] = v;
                }
            }
            __syncthreads();

            unsigned long long a01 = b2_01, a23 = b2_23;
            // x2 = h1[t] @ W2 + b2
#pragma unroll 16
            for (int k = 0; k < KDIM; k++) {
                float hv = s_h[k * NBL + bl];
                unsigned long long hh, u01, u23;
                asm("mov.b64 %0,{%1,%1};" : "=l"(hh) : "r"(__float_as_uint(hv)));
                asm("ld.shared.v2.b64 {%0,%1},[%2];" : "=l"(u01), "=l"(u23)
                    : "r"(a_sW2 + (unsigned)(k * (NJ * 16))));
                asm("fma.rn.f32x2 %0,%1,%2,%0;" : "+l"(a01) : "l"(u01), "l"(hh));
                asm("fma.rn.f32x2 %0,%1,%2,%0;" : "+l"(a23) : "l"(u23), "l"(hh));
            }

            if (t > 0) {
                __syncthreads();               // everyone done reading h1 staging
                const float* src = hist2 + (size_t)(t - 1) * 16384;
#pragma unroll
                for (int i = 0; i < 8; i++) {
                    int idx = tid + i * 256;
                    int jr  = idx >> 3;
                    int q   = idx & 7;
                    float4 v = __ldcg((const float4*)(src + jr * 64 + b0) + q);
                    *(float4*)&s_h[jr * NBL + q * 4] = v;
                }
                __syncthreads();

                // + h2[t-1] @ U2
#pragma unroll 16
                for (int k = 0; k < KDIM; k++) {
                    float hv = s_h[k * NBL + bl];
                    unsigned long long hh, u01, u23;
                    asm("mov.b64 %0,{%1,%1};" : "=l"(hh) : "r"(__float_as_uint(hv)));
                    asm("ld.shared.v2.b64 {%0,%1},[%2];" : "=l"(u01), "=l"(u23)
                        : "r"(a_sU2 + (unsigned)(k * (NJ * 16))));
                    asm("fma.rn.f32x2 %0,%1,%2,%0;" : "+l"(a01) : "l"(u01), "l"(hh));
                    asm("fma.rn.f32x2 %0,%1,%2,%0;" : "+l"(a23) : "l"(u23), "l"(hh));
                }
            }

            unsigned r0, r1, r2, r3;
            asm("mov.b64 {%0,%1},%2;" : "=r"(r0), "=r"(r1) : "l"(a01));
            asm("mov.b64 {%0,%1},%2;" : "=r"(r2), "=r"(r3) : "l"(a23));
            float ig = fsig(__uint_as_float(r0));
            float fg = fsig(__uint_as_float(r1));
            float gg = ftanh_(__uint_as_float(r2));
            float og = fsig(__uint_as_float(r3));
            c2 = fg * c2 + ig * gg;
            float h2 = og * ftanh_(c2);

            hist2[(size_t)t * 16384 + j * 64 + b] = h2;

            __syncthreads();
            if (tid == 0) st_release(&flags2[jb], (unsigned)(t + 1));

            // sequence output (off critical path)
            __stcs(&Hd2[((size_t)t * NB + b) * HID + j], h2);
        }
    }
}

// ---------------------------------------------------------------------------
// Output head: concat(fw, bw) @ dense_W + b, softmax over 5 classes.
// ---------------------------------------------------------------------------
__global__ void __launch_bounds__(256) dense_kernel(
    const float* __restrict__ Wd,
    const float* __restrict__ bd,
    float* __restrict__ out)
{
    __shared__ float sW[2 * HID * NCLASS];
    __shared__ float sb[NCLASS];
    const int tid = threadIdx.x;
    for (int i = tid; i < 2 * HID * NCLASS; i += 256) sW[i] = Wd[i];
    if (tid < NCLASS) sb[tid] = bd[tid];
    __syncthreads();

    int gid = blockIdx.x * 256 + tid;      // b*512 + t
    int b = gid >> 9, t = gid & 511;

    const float* hf = g_H2 + ((size_t)t * NB + b) * HID;
    const float* hb = g_H2 + (size_t)MROWS * HID + ((size_t)(TSTEPS - 1 - t) * NB + b) * HID;

    float acc[NCLASS];
#pragma unroll
    for (int cc = 0; cc < NCLASS; cc++) acc[cc] = sb[cc];

    for (int jj = 0; jj < HID; jj++) {
        float v = hf[jj];
#pragma unroll
        for (int cc = 0; cc < NCLASS; cc++)
            acc[cc] = fmaf(v, sW[jj * NCLASS + cc], acc[cc]);
    }
    for (int jj = 0; jj < HID; jj++) {
        float v = hb[jj];
#pragma unroll
        for (int cc = 0; cc < NCLASS; cc++)
            acc[cc] = fmaf(v, sW[(HID + jj) * NCLASS + cc], acc[cc]);
    }

    float m = acc[0];
#pragma unroll
    for (int cc = 1; cc < NCLASS; cc++) m = fmaxf(m, acc[cc]);
    float e[NCLASS], sum = 0.f;
#pragma unroll
    for (int cc = 0; cc < NCLASS; cc++) { e[cc] = __expf(acc[cc] - m); sum += e[cc]; }
    float inv = __fdividef(1.f, sum);
#pragma unroll
    for (int cc = 0; cc < NCLASS; cc++) out[(size_t)gid * NCLASS + cc] = e[cc] * inv;
}

// ---------------------------------------------------------------------------
// Launcher (graph-capturable: kernel launches only, default stream)
// ---------------------------------------------------------------------------
extern "C" void kernel_launch(void* const* d_in, const int* in_sizes, int n_in,
                              void* d_out, int out_size)
{
    const void*  tokens  = d_in[0];
    const float* embed   = (const float*)d_in[1];
    const float* fw_W1   = (const float*)d_in[2];
    const float* fw_U1   = (const float*)d_in[3];
    const float* fw_b1   = (const float*)d_in[4];
    const float* fw_W2   = (const float*)d_in[5];
    const float* fw_U2   = (const float*)d_in[6];
    const float* fw_b2   = (const float*)d_in[7];
    const float* bw_W1   = (const float*)d_in[8];
    const float* bw_U1   = (const float*)d_in[9];
    const float* bw_b1   = (const float*)d_in[10];
    const float* bw_W2   = (const float*)d_in[11];
    const float* bw_U2   = (const float*)d_in[12];
    const float* bw_b2   = (const float*)d_in[13];
    const float* dense_W = (const float*)d_in[14];
    const float* dense_b = (const float*)d_in[15];
    float* out = (float*)d_out;

    cudaFuncSetAttribute(rec_dual_kernel, cudaFuncAttributeMaxDynamicSharedMemorySize, REC_SMEM);

    prep_kernel<<<1, 256>>>(tokens);

    // Z1 = embed(tokens) @ W1 + b1 (both dirs)
    gemm_kernel<<<dim3(8, 256, 2), 256>>>(embed, tokens, fw_W1, bw_W1, fw_b1, bw_b1);

    // both layers, overlapped wavefronts, 2 CTAs/SM
    rec_dual_kernel<<<256, 256, REC_SMEM>>>(
        fw_U1, bw_U1, fw_W2, bw_W2, fw_b2, bw_b2, fw_U2, bw_U2);

    dense_kernel<<<MROWS / 256, 256>>>(dense_W, dense_b, out);
}

// round 12
// speedup vs baseline: 2.1679x; 2.1679x over previous
#include <cuda_runtime.h>
#include <cstdint>

// ---------------------------------------------------------------------------
// Problem dims
// ---------------------------------------------------------------------------
#define TSTEPS 512
#define NB     64
#define HID    256
#define MROWS  (TSTEPS * NB)      // 32768
#define NCOLS  1024               // 4*HID
#define KDIM   256
#define NCLASS 5

#define GRID_REC 128
#define NJ   32                    // j per CTA
#define NBL  8                     // batches per CTA/group
#define NPROD 8                    // producers per group
#define SHS  260                   // s_h row stride (floats): 16B-aligned rows, bank-skewed
#define FULLMASK 0xffffffffu
#define REC_SMEM ((NJ * 4 * KDIM + NBL * SHS) * 4)   // 128KB U + 8.3KB h

// ---------------------------------------------------------------------------
// Scratch (static __device__ arrays: allocation-free, allowed)
// ---------------------------------------------------------------------------
__device__ __align__(128) float g_Z [2u * MROWS * NCOLS];   // gate preactivations
__device__ __align__(128) float g_H1[2u * MROWS * HID];     // layer-1 hidden outputs
__device__ __align__(128) float g_H2[2u * MROWS * HID];     // layer-2 hidden outputs
__device__ __align__(128) float g_hT[2][2][NB * HID];       // dbl-buf h, [parity][dir][b][j]
__device__ __align__(128) unsigned g_flags[2][16][NPROD];   // [layer][group][producer jb]
__device__ int g_tok32 = 1;                                 // token dtype flag

// ---------------------------------------------------------------------------
// Single-hop message passing primitives
// ---------------------------------------------------------------------------
__device__ __forceinline__ unsigned ld_acquire(const unsigned* p) {
    unsigned v;
    asm volatile("ld.acquire.gpu.global.u32 %0, [%1];" : "=r"(v) : "l"(p) : "memory");
    return v;
}
__device__ __forceinline__ void st_release(unsigned* p, unsigned v) {
    asm volatile("st.release.gpu.global.u32 [%0], %1;" :: "l"(p), "r"(v) : "memory");
}

// ---------------------------------------------------------------------------
// Math helpers
// ---------------------------------------------------------------------------
__device__ __forceinline__ float fsig(float x) {
    x = fminf(fmaxf(x, -30.f), 30.f);
    return __fdividef(1.f, 1.f + __expf(-x));
}
__device__ __forceinline__ float ftanh_(float x) {
    x = fminf(fmaxf(x, -15.f), 15.f);
    float e = __expf(-2.f * x);
    return __fdividef(1.f - e, 1.f + e);
}
__device__ __forceinline__ int load_token(const void* tokens, int is32, int idx) {
    if (is32) return ((const int*)tokens)[idx];
    return (int)((const long long*)tokens)[idx];
}

// ---------------------------------------------------------------------------
// Prep: zero flags (graph replays) + token dtype probe.
// ---------------------------------------------------------------------------
__global__ void prep_kernel(const void* __restrict__ tokens) {
    __shared__ int flag;
    const int tid = threadIdx.x;
    if (tid < 2 * 16 * NPROD) ((unsigned*)g_flags)[tid] = 0u;
    if (tid == 0) flag = 0;
    __syncthreads();
    const int* p = (const int*)tokens;
    int local = 0;
    for (int i = 1 + 2 * tid; i < MROWS; i += 2 * 256) local |= p[i];
    if (local) atomicOr(&flag, 1);
    __syncthreads();
    if (tid == 0) g_tok32 = (flag != 0) ? 1 : 0;
}

// ---------------------------------------------------------------------------
// SGEMM: C[dir] = A @ W[dir] + bias[dir]   (unchanged — isolation)
// ---------------------------------------------------------------------------
__global__ void __launch_bounds__(256) gemm_kernel(
    const float* __restrict__ embed,
    const void*  __restrict__ tokens,
    const float* __restrict__ W_fw,
    const float* __restrict__ W_bw,
    const float* __restrict__ b_fw,
    const float* __restrict__ b_bw,
    int mode)
{
    __shared__ __align__(16) float As[16][132];
    __shared__ __align__(16) float Bs[16][128];
    __shared__ int sTok[128];

    const int tid = threadIdx.x;
    const int dir = blockIdx.z;
    const int m0  = blockIdx.y * 128;
    const int n0  = blockIdx.x * 128;

    const float* Wm   = dir ? W_bw : W_fw;
    const float* bias = dir ? b_bw : b_fw;

    if (mode == 0 && tid < 128) {
        int r = m0 + tid;
        int s = r >> 6, b = r & 63;
        int tt = (dir == 0) ? s : (TSTEPS - 1 - s);
        sTok[tid] = load_token(tokens, g_tok32, b * TSTEPS + tt);
    }
    __syncthreads();

    const int ty = tid >> 4;
    const int tx = tid & 15;

    float acc[8][8];
#pragma unroll
    for (int i = 0; i < 8; i++)
#pragma unroll
        for (int j = 0; j < 8; j++) acc[i][j] = 0.f;

    for (int kt = 0; kt < KDIM; kt += 16) {
#pragma unroll
        for (int i = 0; i < 2; i++) {
            int idx = tid + i * 256;
            int m   = idx >> 2;
            int kq  = idx & 3;
            const float* arow;
            if (mode == 0) arow = embed + (size_t)sTok[m] * KDIM;
            else           arow = g_H1 + (size_t)dir * MROWS * HID + (size_t)(m0 + m) * HID;
            float4 v = *(const float4*)(arow + kt + kq * 4);
            As[kq * 4 + 0][m] = v.x;
            As[kq * 4 + 1][m] = v.y;
            As[kq * 4 + 2][m] = v.z;
            As[kq * 4 + 3][m] = v.w;
        }
#pragma unroll
        for (int i = 0; i < 2; i++) {
            int idx = tid + i * 256;
            int k   = idx >> 5;
            int nq  = idx & 31;
            *(float4*)&Bs[k][nq * 4] =
                *(const float4*)(Wm + (size_t)(kt + k) * NCOLS + n0 + nq * 4);
        }
        __syncthreads();

#pragma unroll
        for (int kk = 0; kk < 16; kk++) {
            float a[8], bb[8];
            *(float4*)&a[0]  = *(const float4*)&As[kk][ty * 8];
            *(float4*)&a[4]  = *(const float4*)&As[kk][ty * 8 + 4];
            *(float4*)&bb[0] = *(const float4*)&Bs[kk][tx * 8];
            *(float4*)&bb[4] = *(const float4*)&Bs[kk][tx * 8 + 4];
#pragma unroll
            for (int i = 0; i < 8; i++)
#pragma unroll
                for (int j = 0; j < 8; j++)
                    acc[i][j] = fmaf(a[i], bb[j], acc[i][j]);
        }
        __syncthreads();
    }

    float bv[8];
#pragma unroll
    for (int j = 0; j < 8; j++) bv[j] = bias[n0 + tx * 8 + j];

    float* Cd = g_Z + (size_t)dir * MROWS * NCOLS;
#pragma unroll
    for (int i = 0; i < 8; i++) {
        size_t r = (size_t)(m0 + ty * 8 + i);
        float* cp = Cd + r * NCOLS + n0 + tx * 8;
        float4 o0, o1;
        o0.x = acc[i][0] + bv[0]; o0.y = acc[i][1] + bv[1];
        o0.z = acc[i][2] + bv[2]; o0.w = acc[i][3] + bv[3];
        o1.x = acc[i][4] + bv[4]; o1.y = acc[i][5] + bv[5];
        o1.z = acc[i][6] + bv[6]; o1.w = acc[i][7] + bv[7];
        *(float4*)cp       = o0;
        *((float4*)cp + 1) = o1;
    }
}

// ---------------------------------------------------------------------------
// Recurrent phase. 128 CTAs x 256 thr. CTA = (dir, bblk 0..7, jb 0..7).
// CTA owns 32 j x 8 b. Group = (dir, bblk): only 8 producers (was 32) ->
// smaller max-skew, 8 flags in ONE 32B sector, 8KB fill (was 32KB).
// h layout [b][j]: producer stores 8x128B contiguous; fill is coalesced
// float4 rows. Matvec: warp = 4j x 8b; per k = 1 LDS.128(U) + 1 LDS(h)
// + mov + 2 FFMA2 (identical issue count to R7). Protocol = R7 verbatim.
// ---------------------------------------------------------------------------
__global__ void __launch_bounds__(256, 1) rec_kernel(
    const float* __restrict__ U_fw,
    const float* __restrict__ U_bw,
    int layer)
{
    extern __shared__ float smem[];
    float* sU  = smem;                      // [k][jj] float4 of 4 gates: 32768 floats
    float* s_h = smem + NJ * 4 * KDIM;      // [bl][k], stride SHS

    const int cid  = blockIdx.x;
    const int dir  = cid >> 6;
    const int bblk = (cid >> 3) & 7;        // 0..7
    const int jb   = cid & 7;               // 0..7  (this CTA's flag index)
    const int j0   = jb * NJ;
    const int b0   = bblk * NBL;
    const int tid  = threadIdx.x;
    const int lane = tid & 31;
    const int jl   = tid >> 3;              // 0..31
    const int bl   = tid & 7;               // 0..7
    const int j    = j0 + jl;
    const int b    = b0 + bl;

    unsigned* flags = g_flags[layer][dir * 8 + bblk];

    const float* U = dir ? U_bw : U_fw;

    // Cache U columns: sU[(k*NJ + jj)*4 + g] = U[k][g*HID + j0+jj]
    for (int idx = tid; idx < NJ * 4 * KDIM; idx += 256) {
        int g  = idx & 3;
        int jj = (idx >> 2) & (NJ - 1);
        int k  = idx >> 7;
        sU[idx] = U[(size_t)k * NCOLS + g * HID + j0 + jj];
    }
    __syncthreads();

    const unsigned a_sU = (unsigned)__cvta_generic_to_shared(sU) + (unsigned)(jl * 16);
    const float* Zd  = g_Z + (size_t)dir * MROWS * NCOLS;
    float* Hd        = (layer ? g_H2 : g_H1) + (size_t)dir * MROWS * HID;
    float* hT0 = g_hT[0][dir];              // [b][j]
    float* hT1 = g_hT[1][dir];

    // first-step Z (streamed)
    size_t zrow0 = (size_t)b * NCOLS;
    float4 z;
    z.x = __ldcs(&Zd[zrow0 + 0 * HID + j]);
    z.y = __ldcs(&Zd[zrow0 + 1 * HID + j]);
    z.z = __ldcs(&Zd[zrow0 + 2 * HID + j]);
    z.w = __ldcs(&Zd[zrow0 + 3 * HID + j]);

    float c = 0.f;

    for (int s = 0; s < TSTEPS; s++) {
        unsigned long long acc01, acc23;
        asm("mov.b64 %0,{%1,%2};" : "=l"(acc01)
            : "r"(__float_as_uint(z.x)), "r"(__float_as_uint(z.y)));
        asm("mov.b64 %0,{%1,%2};" : "=l"(acc23)
            : "r"(__float_as_uint(z.z)), "r"(__float_as_uint(z.w)));

        if (s > 0) {
            // ---- wait: warp 0 polls the 8 producer flags (one 32B sector)
            if (tid < 32) {
                const unsigned tgt = (unsigned)s;
                while (__ballot_sync(FULLMASK,
                        (lane < NPROD) && (ld_acquire(&flags[lane]) < tgt))) { }
            }
            __syncthreads();                 // release warps 1-7; acquire HB

            // ---- fill s_h[bl][k] from g_hT[(s-1)&1][b0..b0+8)[0..256) (coalesced)
            const float* src = (((s - 1) & 1) ? hT1 : hT0) + (size_t)b0 * HID;
#pragma unroll
            for (int i = 0; i < 2; i++) {
                int idx = tid + i * 256;            // 0..511 float4s
                int row = idx >> 6;                 // 0..7 (batch)
                int q   = idx & 63;                 // float4 col
                float4 v = __ldcg((const float4*)(src + row * HID) + q);
                *(float4*)&s_h[row * SHS + q * 4] = v;
            }
            __syncthreads();

            // ---- matvec: z += h @ U (FFMA2, same issue count as R7)
            const float* hrow = s_h + bl * SHS;
#pragma unroll 16
            for (int k = 0; k < KDIM; k++) {
                float hv = hrow[k];
                unsigned long long hh, u01, u23;
                asm("mov.b64 %0,{%1,%1};" : "=l"(hh) : "r"(__float_as_uint(hv)));
                asm("ld.shared.v2.b64 {%0,%1},[%2];" : "=l"(u01), "=l"(u23)
                    : "r"(a_sU + (unsigned)(k * (NJ * 16))));
                asm("fma.rn.f32x2 %0,%1,%2,%0;" : "+l"(acc01) : "l"(u01), "l"(hh));
                asm("fma.rn.f32x2 %0,%1,%2,%0;" : "+l"(acc23) : "l"(u23), "l"(hh));
            }
        }

        unsigned r0, r1, r2, r3;
        asm("mov.b64 {%0,%1},%2;" : "=r"(r0), "=r"(r1) : "l"(acc01));
        asm("mov.b64 {%0,%1},%2;" : "=r"(r2), "=r"(r3) : "l"(acc23));

        float ig = fsig(__uint_as_float(r0));
        float fg = fsig(__uint_as_float(r1));
        float gg = ftanh_(__uint_as_float(r2));
        float og = fsig(__uint_as_float(r3));
        c = fg * c + ig * gg;
        float h = og * ftanh_(c);

        // publish h for next step (dbl-buffered, [b][j]: 8x128B runs)
        float* hTbuf = (s & 1) ? hT1 : hT0;
        hTbuf[(size_t)b * HID + j] = h;

        __syncthreads();                      // all warps' hT stores done (HB)
        if (tid == 0 && s < TSTEPS - 1)
            st_release(&flags[jb], (unsigned)(s + 1));   // single-hop publish

        // off-critical-path: sequence output (streamed) + Z[s+1] prefetch
        __stcs(&Hd[((size_t)s * NB + b) * HID + j], h);
        if (s < TSTEPS - 1) {
            size_t zrow = ((size_t)(s + 1) * NB + b) * NCOLS;
            z.x = __ldcs(&Zd[zrow + 0 * HID + j]);
            z.y = __ldcs(&Zd[zrow + 1 * HID + j]);
            z.z = __ldcs(&Zd[zrow + 2 * HID + j]);
            z.w = __ldcs(&Zd[zrow + 3 * HID + j]);
        }
    }
}

// ---------------------------------------------------------------------------
// Output head: concat(fw, bw) @ dense_W + b, softmax over 5 classes.
// ---------------------------------------------------------------------------
__global__ void __launch_bounds__(256) dense_kernel(
    const float* __restrict__ Wd,
    const float* __restrict__ bd,
    float* __restrict__ out)
{
    __shared__ float sW[2 * HID * NCLASS];
    __shared__ float sb[NCLASS];
    const int tid = threadIdx.x;
    for (int i = tid; i < 2 * HID * NCLASS; i += 256) sW[i] = Wd[i];
    if (tid < NCLASS) sb[tid] = bd[tid];
    __syncthreads();

    int gid = blockIdx.x * 256 + tid;      // b*512 + t
    int b = gid >> 9, t = gid & 511;

    const float* hf = g_H2 + ((size_t)t * NB + b) * HID;
    const float* hb = g_H2 + (size_t)MROWS * HID + ((size_t)(TSTEPS - 1 - t) * NB + b) * HID;

    float acc[NCLASS];
#pragma unroll
    for (int cc = 0; cc < NCLASS; cc++) acc[cc] = sb[cc];

    for (int jj = 0; jj < HID; jj++) {
        float v = hf[jj];
#pragma unroll
        for (int cc = 0; cc < NCLASS; cc++)
            acc[cc] = fmaf(v, sW[jj * NCLASS + cc], acc[cc]);
    }
    for (int jj = 0; jj < HID; jj++) {
        float v = hb[jj];
#pragma unroll
        for (int cc = 0; cc < NCLASS; cc++)
            acc[cc] = fmaf(v, sW[(HID + jj) * NCLASS + cc], acc[cc]);
    }

    float m = acc[0];
#pragma unroll
    for (int cc = 1; cc < NCLASS; cc++) m = fmaxf(m, acc[cc]);
    float e[NCLASS], sum = 0.f;
#pragma unroll
    for (int cc = 0; cc < NCLASS; cc++) { e[cc] = __expf(acc[cc] - m); sum += e[cc]; }
    float inv = __fdividef(1.f, sum);
#pragma unroll
    for (int cc = 0; cc < NCLASS; cc++) out[(size_t)gid * NCLASS + cc] = e[cc] * inv;
}

// ---------------------------------------------------------------------------
// Launcher (graph-capturable: kernel launches only, default stream)
// ---------------------------------------------------------------------------
extern "C" void kernel_launch(void* const* d_in, const int* in_sizes, int n_in,
                              void* d_out, int out_size)
{
    const void*  tokens  = d_in[0];
    const float* embed   = (const float*)d_in[1];
    const float* fw_W1   = (const float*)d_in[2];
    const float* fw_U1   = (const float*)d_in[3];
    const float* fw_b1   = (const float*)d_in[4];
    const float* fw_W2   = (const float*)d_in[5];
    const float* fw_U2   = (const float*)d_in[6];
    const float* fw_b2   = (const float*)d_in[7];
    const float* bw_W1   = (const float*)d_in[8];
    const float* bw_U1   = (const float*)d_in[9];
    const float* bw_b1   = (const float*)d_in[10];
    const float* bw_W2   = (const float*)d_in[11];
    const float* bw_U2   = (const float*)d_in[12];
    const float* bw_b2   = (const float*)d_in[13];
    const float* dense_W = (const float*)d_in[14];
    const float* dense_b = (const float*)d_in[15];
    float* out = (float*)d_out;

    cudaFuncSetAttribute(rec_kernel, cudaFuncAttributeMaxDynamicSharedMemorySize, REC_SMEM);

    prep_kernel<<<1, 256>>>(tokens);

    gemm_kernel<<<dim3(8, 256, 2), 256>>>(embed, tokens, fw_W1, bw_W1, fw_b1, bw_b1, 0);
    rec_kernel<<<GRID_REC, 256, REC_SMEM>>>(fw_U1, bw_U1, 0);
    gemm_kernel<<<dim3(8, 256, 2), 256>>>(embed, tokens, fw_W2, bw_W2, fw_b2, bw_b2, 1);
    rec_kernel<<<GRID_REC, 256, REC_SMEM>>>(fw_U2, bw_U2, 1);
    dense_kernel<<<MROWS / 256, 256>>>(dense_W, dense_b, out);
}